// round 7
// baseline (speedup 1.0000x reference)
#include <cuda_runtime.h>
#include <math.h>

#define F 64
#define MAXN 100000
#define MAXE 1600000
#define SLOPE 0.2f
#define KT 32   // GEMM k-tile

// ---------------- device scratch (static, no runtime alloc) ----------------
__device__ float g_z[(size_t)MAXN * F];     // projected features [N,64]
__device__ int   g_cnt[MAXN];               // in-degree histogram
__device__ int   g_cnt2[MAXN];              // fill cursors
__device__ int   g_tmp[MAXN];               // inclusive scan temp
__device__ int   g_rowptr[MAXN + 1];        // CSR offsets
__device__ int   g_src_sorted[MAXE];        // src ids grouped by dst
__device__ int   g_blocksum[128];
__device__ int   g_blockoff[128];

// ---------------- packed f32x2 helpers (sm_100+ PTX) ------------------------
__device__ __forceinline__ unsigned long long pack2(float lo, float hi) {
    unsigned long long r;
    asm("mov.b64 %0, {%1, %2};" : "=l"(r) : "f"(lo), "f"(hi));
    return r;
}
__device__ __forceinline__ void unpack2(unsigned long long v, float& lo, float& hi) {
    asm("mov.b64 {%0, %1}, %2;" : "=f"(lo), "=f"(hi) : "l"(v));
}
__device__ __forceinline__ void fma2(unsigned long long& d,
                                     unsigned long long a, unsigned long long b) {
    asm("fma.rn.f32x2 %0, %1, %2, %0;" : "+l"(d) : "l"(a), "l"(b));
}

// ---------------- cp.async helpers ------------------------------------------
__device__ __forceinline__ void cpa4(unsigned dst, const float* src, bool ok) {
    asm volatile("cp.async.ca.shared.global [%0], [%1], 4, %2;"
                 :: "r"(dst), "l"(src), "r"(ok ? 4u : 0u));
}
__device__ __forceinline__ void cpa16(unsigned dst, const float* src, bool ok) {
    asm volatile("cp.async.cg.shared.global [%0], [%1], 16, %2;"
                 :: "r"(dst), "l"(src), "r"(ok ? 16u : 0u));
}
__device__ __forceinline__ void cpa_commit() {
    asm volatile("cp.async.commit_group;");
}
template <int N>
__device__ __forceinline__ void cpa_wait() {
    asm volatile("cp.async.wait_group %0;" :: "n"(N));
}

// ---------------- merged projection GEMM ------------------------------------
// One launch covers both matrices: blocks [0, nbd) -> d_sim @ W_d,
// blocks [nbd, nbd+nbm) -> mi_sim @ W_mi. 64x64 tile, 256 threads,
// double-buffered cp.async smem pipeline, f32x2 packed FMA inner loop.
__global__ void __launch_bounds__(256) gemm_dual(
        const float* __restrict__ d_sim,  const float* __restrict__ W_d,
        const float* __restrict__ mi_sim, const float* __restrict__ W_mi,
        int ND, int NM, int KD, int KM) {
    __shared__ __align__(16) float As[2][KT][68];   // padded: stride 68 -> 4-way max
    __shared__ __align__(16) float Bs[2][KT][64];

    const int nbd = (ND + 63) >> 6;
    const float* A; const float* W; int M, K, zoff, m0;
    if ((int)blockIdx.x < nbd) {
        A = d_sim;  W = W_d;  M = ND; K = KD; zoff = 0;
        m0 = blockIdx.x * 64;
    } else {
        A = mi_sim; W = W_mi; M = NM; K = KM; zoff = ND;
        m0 = (blockIdx.x - nbd) * 64;
    }

    const int tid = threadIdx.x;
    const int tx = tid & 15, ty = tid >> 4;

    auto load_tile = [&](int buf, int kk) {
        // A tile: 64 rows x KT cols, transposed into As[c][r]
        unsigned sa = (unsigned)__cvta_generic_to_shared(&As[buf][0][0]);
#pragma unroll
        for (int i = 0; i < 8; i++) {
            int idx = tid + i * 256;           // 0..2047
            int r = idx >> 5, c = idx & 31;
            int row = m0 + r, col = kk + c;
            bool ok = (row < M) && (col < K);
            const float* sp = ok ? (A + (size_t)row * K + col) : A;
            cpa4(sa + (unsigned)(c * 68 + r) * 4u, sp, ok);
        }
        // B tile: KT rows x 64 cols, 16B vector copies
        unsigned sb = (unsigned)__cvta_generic_to_shared(&Bs[buf][0][0]);
#pragma unroll
        for (int i = 0; i < 2; i++) {
            int idx = tid + i * 256;           // 0..511
            int c = idx >> 4, n4 = idx & 15;
            int col = kk + c;
            bool ok = (col < K);
            const float* sp = ok ? (W + (size_t)col * F + n4 * 4) : W;
            cpa16(sb + (unsigned)(c * 64 + n4 * 4) * 4u, sp, ok);
        }
    };

    unsigned long long acc2[4][2];
#pragma unroll
    for (int i = 0; i < 4; i++) { acc2[i][0] = 0ull; acc2[i][1] = 0ull; }

    load_tile(0, 0);
    cpa_commit();

    int buf = 0;
    for (int kk = 0; kk < K; kk += KT) {
        if (kk + KT < K) {
            load_tile(buf ^ 1, kk + KT);
            cpa_commit();
            cpa_wait<1>();          // current buf's group done; next in flight
        } else {
            cpa_wait<0>();
        }
        __syncthreads();

#pragma unroll
        for (int c = 0; c < KT; c++) {
            float4 a4 = *(const float4*)&As[buf][c][ty << 2];
            float4 b4 = *(const float4*)&Bs[buf][c][tx << 2];
            unsigned long long b01 = pack2(b4.x, b4.y);
            unsigned long long b23 = pack2(b4.z, b4.w);
            float av[4] = {a4.x, a4.y, a4.z, a4.w};
#pragma unroll
            for (int i = 0; i < 4; i++) {
                unsigned long long aa = pack2(av[i], av[i]);
                fma2(acc2[i][0], aa, b01);
                fma2(acc2[i][1], aa, b23);
            }
        }
        __syncthreads();
        buf ^= 1;
    }

#pragma unroll
    for (int i = 0; i < 4; i++) {
        int row = m0 + (ty << 2) + i;
        if (row < M) {
            float4 v;
            unpack2(acc2[i][0], v.x, v.y);
            unpack2(acc2[i][1], v.z, v.w);
            *(float4*)&g_z[(size_t)(zoff + row) * F + (tx << 2)] = v;
        }
    }
}

// ---------------- CSR build -------------------------------------------------
__global__ void zero_counts(int n) {
    int i = blockIdx.x * blockDim.x + threadIdx.x;
    if (i < n) { g_cnt[i] = 0; g_cnt2[i] = 0; }
}

__global__ void count_kernel(const int* __restrict__ dst, int E) {
    int i = blockIdx.x * blockDim.x + threadIdx.x;
    if (i < E) atomicAdd(&g_cnt[dst[i]], 1);
}

__global__ void scan1(int n) {
    __shared__ int sh[1024];
    int i = blockIdx.x * 1024 + threadIdx.x;
    int v = (i < n) ? g_cnt[i] : 0;
    sh[threadIdx.x] = v;
    __syncthreads();
    for (int off = 1; off < 1024; off <<= 1) {
        int t = (threadIdx.x >= off) ? sh[threadIdx.x - off] : 0;
        __syncthreads();
        sh[threadIdx.x] += t;
        __syncthreads();
    }
    if (i < n) g_tmp[i] = sh[threadIdx.x];
    if (threadIdx.x == 1023) g_blocksum[blockIdx.x] = sh[1023];
}

__global__ void scan2(int nb) {
    if (threadIdx.x == 0) {
        int run = 0;
        for (int b = 0; b < nb; b++) {
            g_blockoff[b] = run;
            run += g_blocksum[b];
        }
    }
}

__global__ void scan3(int n, int E) {
    int i = blockIdx.x * blockDim.x + threadIdx.x;
    if (i < n) g_rowptr[i] = g_tmp[i] - g_cnt[i] + g_blockoff[i >> 10];
    if (i == 0) g_rowptr[n] = E;
}

__global__ void fill_kernel(const int* __restrict__ src, const int* __restrict__ dst, int E) {
    int i = blockIdx.x * blockDim.x + threadIdx.x;
    if (i < E) {
        int d = dst[i];
        int pos = g_rowptr[d] + atomicAdd(&g_cnt2[d], 1);
        g_src_sorted[pos] = src[i];
    }
}

// ---------------- per-dst-node ONLINE softmax + aggregate (warp per node) ---
// Single pass, 4 edges per iteration: 4-deep gather MLP, 4 interleaved
// shuffle chains, one online-softmax correction per 4 edges.
__global__ void __launch_bounds__(256) node_kernel(float* __restrict__ out, int NN) {
    int gwid = (blockIdx.x * blockDim.x + threadIdx.x) >> 5;
    int lane = threadIdx.x & 31;
    if (gwid >= NN) return;
    const int node = gwid;
    const int beg = g_rowptr[node];
    const int end = g_rowptr[node + 1];

    const float2* z2 = (const float2*)g_z;
    float2 zd = z2[(size_t)node * 32 + lane];

    float m = -INFINITY;
    float denom = 0.f;
    float2 acc = make_float2(0.f, 0.f);

    int p = beg;
    for (; p + 3 < end; p += 4) {
        int s0 = g_src_sorted[p];
        int s1 = g_src_sorted[p + 1];
        int s2 = g_src_sorted[p + 2];
        int s3 = g_src_sorted[p + 3];
        float2 a0 = z2[(size_t)s0 * 32 + lane];
        float2 a1 = z2[(size_t)s1 * 32 + lane];
        float2 a2 = z2[(size_t)s2 * 32 + lane];
        float2 a3 = z2[(size_t)s3 * 32 + lane];
        float d0 = a0.x * zd.x + a0.y * zd.y;
        float d1 = a1.x * zd.x + a1.y * zd.y;
        float d2 = a2.x * zd.x + a2.y * zd.y;
        float d3 = a3.x * zd.x + a3.y * zd.y;
#pragma unroll
        for (int off = 16; off; off >>= 1) {
            d0 += __shfl_xor_sync(0xffffffffu, d0, off);
            d1 += __shfl_xor_sync(0xffffffffu, d1, off);
            d2 += __shfl_xor_sync(0xffffffffu, d2, off);
            d3 += __shfl_xor_sync(0xffffffffu, d3, off);
        }
        float e0 = d0 > 0.f ? d0 : SLOPE * d0;
        float e1 = d1 > 0.f ? d1 : SLOPE * d1;
        float e2 = d2 > 0.f ? d2 : SLOPE * d2;
        float e3 = d3 > 0.f ? d3 : SLOPE * d3;
        float mn = fmaxf(fmaxf(m, fmaxf(e0, e1)), fmaxf(e2, e3));
        float corr = __expf(m - mn);        // exp(-inf)=0 on first group
        float w0 = __expf(e0 - mn);
        float w1 = __expf(e1 - mn);
        float w2 = __expf(e2 - mn);
        float w3 = __expf(e3 - mn);
        m = mn;
        denom = fmaf(denom, corr, (w0 + w1) + (w2 + w3));
        float sx = fmaf(w0, a0.x, w1 * a1.x) + fmaf(w2, a2.x, w3 * a3.x);
        float sy = fmaf(w0, a0.y, w1 * a1.y) + fmaf(w2, a2.y, w3 * a3.y);
        acc.x = fmaf(acc.x, corr, sx);
        acc.y = fmaf(acc.y, corr, sy);
    }
    for (; p < end; p++) {
        int s = g_src_sorted[p];
        float2 a = z2[(size_t)s * 32 + lane];
        float d0 = a.x * zd.x + a.y * zd.y;
#pragma unroll
        for (int off = 16; off; off >>= 1)
            d0 += __shfl_xor_sync(0xffffffffu, d0, off);
        float e = d0 > 0.f ? d0 : SLOPE * d0;
        float mn = fmaxf(m, e);
        float corr = __expf(m - mn);
        float w = __expf(e - mn);
        m = mn;
        denom = fmaf(denom, corr, w);
        acc.x = fmaf(acc.x, corr, w * a.x);
        acc.y = fmaf(acc.y, corr, w * a.y);
    }

    float2 h = make_float2(0.f, 0.f);
    if (end > beg) {
        float inv = 1.f / denom;
        h.x = acc.x * inv;
        h.y = acc.y * inv;
    }
    // ELU
    h.x = h.x > 0.f ? h.x : expm1f(h.x);
    h.y = h.y > 0.f ? h.y : expm1f(h.y);
    ((float2*)out)[(size_t)node * 32 + lane] = h;
}

// ---------------- launch ----------------------------------------------------
extern "C" void kernel_launch(void* const* d_in, const int* in_sizes, int n_in,
                              void* d_out, int out_size) {
    const float* d_sim  = (const float*)d_in[0];
    const float* mi_sim = (const float*)d_in[1];
    const float* W_d    = (const float*)d_in[2];
    const float* W_mi   = (const float*)d_in[3];
    const int*   src    = (const int*)d_in[4];
    const int*   dst    = (const int*)d_in[5];
    float* out = (float*)d_out;

    const int KD = 383, KM = 495;
    const int ND = in_sizes[0] / KD;
    const int NM = in_sizes[1] / KM;
    const int NN = ND + NM;
    const int E  = in_sizes[4];

    const int nbd = (ND + 63) / 64;
    const int nbm = (NM + 63) / 64;
    gemm_dual<<<nbd + nbm, 256>>>(d_sim, W_d, mi_sim, W_mi, ND, NM, KD, KM);

    zero_counts<<<(NN + 255) / 256, 256>>>(NN);
    count_kernel<<<(E + 255) / 256, 256>>>(dst, E);

    int nb = (NN + 1023) / 1024;
    scan1<<<nb, 1024>>>(NN);
    scan2<<<1, 32>>>(nb);
    scan3<<<(NN + 255) / 256, 256>>>(NN, E);

    fill_kernel<<<(E + 255) / 256, 256>>>(src, dst, E);

    node_kernel<<<(NN * 32 + 255) / 256, 256>>>(out, NN);
}